// round 1
// baseline (speedup 1.0000x reference)
#include <cuda_runtime.h>
#include <math.h>

#define DIMM 4096
#define HEADD 128
#define NHQ 32
#define NHKV 8
#define HIDDEN 11008
#define BATCH 32
#define MAXSEQ 2048
#define STARTPOS 1024
#define SEQL (STARTPOS + 1)
#define EPS 1e-5f
#define KT 128

typedef unsigned long long u64;

// ---------- f32x2 packed helpers (sm_103a) ----------
__device__ __forceinline__ u64 fma2(u64 a, u64 b, u64 c) {
    u64 d;
    asm("fma.rn.f32x2 %0, %1, %2, %3;" : "=l"(d) : "l"(a), "l"(b), "l"(c));
    return d;
}
__device__ __forceinline__ u64 bcast2(float x) {
    u64 r;
    asm("mov.b64 %0, {%1, %1};" : "=l"(r) : "f"(x));
    return r;
}
__device__ __forceinline__ float2 unpk(u64 a) {
    float2 f;
    asm("mov.b64 {%0, %1}, %2;" : "=f"(f.x), "=f"(f.y) : "l"(a));
    return f;
}

// ---------- scratch (device globals; no allocation allowed) ----------
__device__ __align__(16) float g_hT[DIMM * BATCH];          // rmsnorm1 out, transposed [k][b]
__device__ __align__(16) float g_q[BATCH * NHQ * HEADD];    // roped q, b-major
__device__ __align__(16) float g_knew[BATCH * NHKV * HEADD];
__device__ __align__(16) float g_vnew[BATCH * NHKV * HEADD];
__device__ __align__(16) float g_attnT[DIMM * BATCH];       // attention out, transposed
__device__ __align__(16) float g_res2[BATCH * DIMM];        // after wo + residual, b-major
__device__ __align__(16) float g_h2T[DIMM * BATCH];         // ffn-normed, transposed
__device__ __align__(16) float g_gateT[HIDDEN * BATCH];     // silu(w1)*w3, transposed
__device__ __align__(16) float2 g_P1[32 * 6144 * 16];       // split-K partials (25.2MB)
__device__ __align__(16) float2 g_P2[16 * 11008 * 16];      // gate second partials

// ---------- rmsnorm: reads b-major x, writes transposed yT[k*32+b] ----------
__global__ void __launch_bounds__(256) rmsnorm_kernel(
    const float* __restrict__ x, const float* __restrict__ w, float* __restrict__ yT)
{
    int b = blockIdx.x;
    const float* xr = x + (size_t)b * DIMM;
    __shared__ float red[32];
    float ss = 0.f;
    for (int i = threadIdx.x; i < DIMM; i += 256) { float v = xr[i]; ss += v * v; }
    #pragma unroll
    for (int o = 16; o; o >>= 1) ss += __shfl_xor_sync(0xffffffffu, ss, o);
    if ((threadIdx.x & 31) == 0) red[threadIdx.x >> 5] = ss;
    __syncthreads();
    if (threadIdx.x < 32) {
        float v = (threadIdx.x < 8) ? red[threadIdx.x] : 0.f;
        #pragma unroll
        for (int o = 16; o; o >>= 1) v += __shfl_xor_sync(0xffffffffu, v, o);
        if (threadIdx.x == 0) red[0] = v;
    }
    __syncthreads();
    float inv = 1.0f / (sqrtf(red[0] * (1.0f / DIMM)) + EPS);
    for (int i = threadIdx.x; i < DIMM; i += 256)
        yT[(size_t)i * BATCH + b] = w[i] * xr[i] * inv;
}

// ---------- GEMV core: thread owns 2 columns, 32 batches as 16 f32x2 accs ----------
__device__ __forceinline__ void gemv_core2(
    const float* __restrict__ XT, const float* __restrict__ W, int ldW,
    int col, int k0, int k1, float2* __restrict__ Pout)
{
    __shared__ __align__(16) float sh[KT * BATCH];
    const u64* sh2 = (const u64*)sh;
    u64 acc0[16], acc1[16];
    #pragma unroll
    for (int p = 0; p < 16; p++) { acc0[p] = 0ull; acc1[p] = 0ull; }

    for (int kt = k0; kt < k1; kt += KT) {
        const float4* src = (const float4*)(XT + (size_t)kt * BATCH);
        float4* dstv = (float4*)sh;
        #pragma unroll
        for (int i = 0; i < 4; i++) dstv[threadIdx.x + i * 256] = src[threadIdx.x + i * 256];
        __syncthreads();
        const float* wp = W + (size_t)kt * ldW + col;
        #pragma unroll 4
        for (int k = 0; k < KT; k++) {
            float w0 = wp[(size_t)k * ldW];
            float w1 = wp[(size_t)k * ldW + 256];
            u64 ww0 = bcast2(w0), ww1 = bcast2(w1);
            #pragma unroll
            for (int p = 0; p < 16; p++) {
                u64 h = sh2[k * 16 + p];
                acc0[p] = fma2(h, ww0, acc0[p]);
                acc1[p] = fma2(h, ww1, acc1[p]);
            }
        }
        __syncthreads();
    }
    #pragma unroll
    for (int p = 0; p < 16; p++) {
        Pout[p] = unpk(acc0[p]);
        Pout[256 * 16 + p] = unpk(acc1[p]);
    }
}

// fused qkv: columns 0..4095 wq, 4096..5119 wk, 5120..6143 wv
__global__ void __launch_bounds__(256) gemv_qkv_kernel(
    const float* __restrict__ XT, const float* __restrict__ wq,
    const float* __restrict__ wk, const float* __restrict__ wv,
    float2* __restrict__ P, int kchunk)
{
    int nbase = blockIdx.x * 512;
    const float* W; int ld, nloc;
    if (nbase < 4096)      { W = wq; ld = 4096; nloc = nbase; }
    else if (nbase < 5120) { W = wk; ld = 1024; nloc = nbase - 4096; }
    else                   { W = wv; ld = 1024; nloc = nbase - 5120; }
    int k0 = blockIdx.y * kchunk;
    int k1 = min(k0 + kchunk, 4096);
    gemv_core2(XT, W, ld, nloc + threadIdx.x, k0, k1,
               P + ((size_t)blockIdx.y * 6144 + nbase + threadIdx.x) * 16);
}

__global__ void __launch_bounds__(256) gemv_single_kernel(
    const float* __restrict__ XT, const float* __restrict__ W,
    float2* __restrict__ P, int K, int N, int kchunk)
{
    int nbase = blockIdx.x * 512;
    int k0 = blockIdx.y * kchunk;
    int k1 = min(k0 + kchunk, K);
    gemv_core2(XT, W, N, nbase + threadIdx.x, k0, k1,
               P + ((size_t)blockIdx.y * N + nbase + threadIdx.x) * 16);
}

// gate GEMV: one column per thread, two weight matrices
__global__ void __launch_bounds__(256) gemv_gate_kernel(
    const float* __restrict__ XT, const float* __restrict__ W1, const float* __restrict__ W3,
    float2* __restrict__ P1, float2* __restrict__ P2, int kchunk)
{
    __shared__ __align__(16) float sh[KT * BATCH];
    const u64* sh2 = (const u64*)sh;
    int n = blockIdx.x * 256 + threadIdx.x;
    u64 a1[16], a3[16];
    #pragma unroll
    for (int p = 0; p < 16; p++) { a1[p] = 0ull; a3[p] = 0ull; }
    int k0 = blockIdx.y * kchunk;
    int k1 = min(k0 + kchunk, 4096);
    for (int kt = k0; kt < k1; kt += KT) {
        const float4* src = (const float4*)(XT + (size_t)kt * BATCH);
        float4* dstv = (float4*)sh;
        #pragma unroll
        for (int i = 0; i < 4; i++) dstv[threadIdx.x + i * 256] = src[threadIdx.x + i * 256];
        __syncthreads();
        const float* p1 = W1 + (size_t)kt * HIDDEN + n;
        const float* p3 = W3 + (size_t)kt * HIDDEN + n;
        #pragma unroll 4
        for (int k = 0; k < KT; k++) {
            u64 ww1 = bcast2(p1[(size_t)k * HIDDEN]);
            u64 ww3 = bcast2(p3[(size_t)k * HIDDEN]);
            #pragma unroll
            for (int p = 0; p < 16; p++) {
                u64 h = sh2[k * 16 + p];
                a1[p] = fma2(h, ww1, a1[p]);
                a3[p] = fma2(h, ww3, a3[p]);
            }
        }
        __syncthreads();
    }
    size_t off = ((size_t)blockIdx.y * HIDDEN + n) * 16;
    #pragma unroll
    for (int p = 0; p < 16; p++) { P1[off + p] = unpk(a1[p]); P2[off + p] = unpk(a3[p]); }
}

// ---------- split-K reduces ----------
// qkv reduce + RoPE fused. Thread owns a column-pair (even n0, odd n1).
__global__ void __launch_bounds__(256) reduce_qkv_rope_kernel(
    const float2* __restrict__ P, const float* __restrict__ fcos, const float* __restrict__ fsin,
    float* __restrict__ q, float* __restrict__ knew, float* __restrict__ vnew)
{
    int pairidx = blockIdx.x * 256 + threadIdx.x;   // 0..3071
    int n0 = pairidx * 2;
    float2 a[16], c[16];
    #pragma unroll
    for (int p = 0; p < 16; p++) { a[p] = make_float2(0.f, 0.f); c[p] = make_float2(0.f, 0.f); }
    for (int kz = 0; kz < 32; kz++) {
        const float2* p0 = P + ((size_t)kz * 6144 + n0) * 16;
        #pragma unroll
        for (int p = 0; p < 16; p++) {
            float2 u = p0[p];      a[p].x += u.x; a[p].y += u.y;
            float2 w = p0[16 + p]; c[p].x += w.x; c[p].y += w.y;
        }
    }
    if (n0 < 5120) {
        int i = (n0 >> 1) & 63;
        float cc = fcos[i], sn = fsin[i];
        float* dst; int h, d0, hstride;
        if (n0 < 4096) { h = n0 >> 7; d0 = n0 & 127; dst = q; hstride = NHQ; }
        else { int m = n0 - 4096; h = m >> 7; d0 = m & 127; dst = knew; hstride = NHKV; }
        #pragma unroll
        for (int p = 0; p < 16; p++) {
            int b0 = 2 * p;
            dst[(b0 * hstride + h) * HEADD + d0]     = a[p].x * cc - c[p].x * sn;
            dst[(b0 * hstride + h) * HEADD + d0 + 1] = a[p].x * sn + c[p].x * cc;
            dst[((b0 + 1) * hstride + h) * HEADD + d0]     = a[p].y * cc - c[p].y * sn;
            dst[((b0 + 1) * hstride + h) * HEADD + d0 + 1] = a[p].y * sn + c[p].y * cc;
        }
    } else {
        int m = n0 - 5120; int g = m >> 7, d0 = m & 127;
        #pragma unroll
        for (int p = 0; p < 16; p++) {
            int b0 = 2 * p;
            vnew[(b0 * NHKV + g) * HEADD + d0]       = a[p].x;
            vnew[(b0 * NHKV + g) * HEADD + d0 + 1]   = c[p].x;
            vnew[((b0 + 1) * NHKV + g) * HEADD + d0]     = a[p].y;
            vnew[((b0 + 1) * NHKV + g) * HEADD + d0 + 1] = c[p].y;
        }
    }
}

__global__ void __launch_bounds__(256) reduce_addres_kernel(
    const float2* __restrict__ P, const float* __restrict__ res, float* __restrict__ out,
    int N, int SK)
{
    int n = blockIdx.x * 256 + threadIdx.x;
    float2 a[16];
    #pragma unroll
    for (int p = 0; p < 16; p++) a[p] = make_float2(0.f, 0.f);
    for (int kz = 0; kz < SK; kz++) {
        const float2* p0 = P + ((size_t)kz * N + n) * 16;
        #pragma unroll
        for (int p = 0; p < 16; p++) { float2 u = p0[p]; a[p].x += u.x; a[p].y += u.y; }
    }
    #pragma unroll
    for (int p = 0; p < 16; p++) {
        out[(size_t)(2 * p) * N + n]     = a[p].x + res[(size_t)(2 * p) * N + n];
        out[(size_t)(2 * p + 1) * N + n] = a[p].y + res[(size_t)(2 * p + 1) * N + n];
    }
}

__global__ void __launch_bounds__(256) reduce_gate_kernel(
    const float2* __restrict__ P1, const float2* __restrict__ P2, float* __restrict__ gT)
{
    int n = blockIdx.x * 256 + threadIdx.x;
    float2 a[16], g3[16];
    #pragma unroll
    for (int p = 0; p < 16; p++) { a[p] = make_float2(0.f, 0.f); g3[p] = make_float2(0.f, 0.f); }
    for (int kz = 0; kz < 16; kz++) {
        const float2* p1 = P1 + ((size_t)kz * HIDDEN + n) * 16;
        const float2* p3 = P2 + ((size_t)kz * HIDDEN + n) * 16;
        #pragma unroll
        for (int p = 0; p < 16; p++) {
            float2 u = p1[p]; a[p].x += u.x; a[p].y += u.y;
            float2 w = p3[p]; g3[p].x += w.x; g3[p].y += w.y;
        }
    }
    float* dst = gT + (size_t)n * BATCH;
    #pragma unroll
    for (int p = 0; p < 16; p++) {
        float v1 = a[p].x, v3 = g3[p].x;
        dst[2 * p] = (v1 / (1.f + expf(-v1))) * v3;
        float u1 = a[p].y, u3 = g3[p].y;
        dst[2 * p + 1] = (u1 / (1.f + expf(-u1))) * u3;
    }
}

// ---------- attention: block per (kv-head g, batch b), 4 q-heads ----------
__global__ void __launch_bounds__(256) attn_kernel(
    const float* __restrict__ cache_k, const float* __restrict__ cache_v,
    const float* __restrict__ q, const float* __restrict__ knew, const float* __restrict__ vnew,
    float* __restrict__ outT)
{
    int g = blockIdx.x, b = blockIdx.y;
    __shared__ __align__(16) float sc[4][1056];
    __shared__ __align__(16) float qs[4][HEADD];
    __shared__ float red[64];
    __shared__ float inv_s[4];
    __shared__ float acc1[4][HEADD];
    int tid = threadIdx.x;

    for (int i = tid; i < 4 * HEADD; i += 256) {
        int r = i >> 7, d = i & 127;
        qs[r][d] = q[((size_t)b * NHQ + (g * 4 + r)) * HEADD + d];
    }
    __syncthreads();

    int warp = tid >> 5, lane = tid & 31;
    float ql[4][4];
    #pragma unroll
    for (int r = 0; r < 4; r++) {
        float4 t = *(const float4*)&qs[r][lane * 4];
        ql[r][0] = t.x; ql[r][1] = t.y; ql[r][2] = t.z; ql[r][3] = t.w;
    }
    const float scale = 0.08838834764831845f;  // 1/sqrt(128)

    for (int l = warp; l < SEQL; l += 8) {
        const float* kp = (l < STARTPOS)
            ? (cache_k + (((size_t)b * MAXSEQ + l) * NHKV + g) * HEADD)
            : (knew + ((size_t)b * NHKV + g) * HEADD);
        float4 kv = *(const float4*)(kp + lane * 4);
        float p0 = kv.x * ql[0][0] + kv.y * ql[0][1] + kv.z * ql[0][2] + kv.w * ql[0][3];
        float p1 = kv.x * ql[1][0] + kv.y * ql[1][1] + kv.z * ql[1][2] + kv.w * ql[1][3];
        float p2 = kv.x * ql[2][0] + kv.y * ql[2][1] + kv.z * ql[2][2] + kv.w * ql[2][3];
        float p3 = kv.x * ql[3][0] + kv.y * ql[3][1] + kv.z * ql[3][2] + kv.w * ql[3][3];
        #pragma unroll
        for (int o = 16; o; o >>= 1) {
            p0 += __shfl_xor_sync(0xffffffffu, p0, o);
            p1 += __shfl_xor_sync(0xffffffffu, p1, o);
            p2 += __shfl_xor_sync(0xffffffffu, p2, o);
            p3 += __shfl_xor_sync(0xffffffffu, p3, o);
        }
        if (lane == 0) {
            sc[0][l] = p0 * scale; sc[1][l] = p1 * scale;
            sc[2][l] = p2 * scale; sc[3][l] = p3 * scale;
        }
    }
    __syncthreads();

    // softmax: 64 threads per head
    {
        int r = tid >> 6;
        float m = -1e30f;
        for (int l = (tid & 63); l < SEQL; l += 64) m = fmaxf(m, sc[r][l]);
        #pragma unroll
        for (int o = 16; o; o >>= 1) m = fmaxf(m, __shfl_xor_sync(0xffffffffu, m, o));
        if (lane == 0) red[warp] = m;
        __syncthreads();
        m = fmaxf(red[2 * r], red[2 * r + 1]);
        float s = 0.f;
        for (int l = (tid & 63); l < SEQL; l += 64) {
            float e = expf(sc[r][l] - m);
            sc[r][l] = e; s += e;
        }
        #pragma unroll
        for (int o = 16; o; o >>= 1) s += __shfl_xor_sync(0xffffffffu, s, o);
        __syncthreads();
        if (lane == 0) red[warp] = s;
        __syncthreads();
        s = red[2 * r] + red[2 * r + 1];
        if ((tid & 63) == 0) inv_s[r] = 1.0f / s;
    }
    __syncthreads();

    // weighted V sum: thread -> dim d, two l-halves
    int d = tid & 127, half = tid >> 7;
    float a0 = 0, a1 = 0, a2 = 0, a3 = 0;
    for (int l = half; l < SEQL; l += 2) {
        float v = (l < STARTPOS)
            ? cache_v[(((size_t)b * MAXSEQ + l) * NHKV + g) * HEADD + d]
            : vnew[((size_t)b * NHKV + g) * HEADD + d];
        a0 += sc[0][l] * v; a1 += sc[1][l] * v; a2 += sc[2][l] * v; a3 += sc[3][l] * v;
    }
    if (half == 1) { acc1[0][d] = a0; acc1[1][d] = a1; acc1[2][d] = a2; acc1[3][d] = a3; }
    __syncthreads();
    if (half == 0) {
        a0 += acc1[0][d]; a1 += acc1[1][d]; a2 += acc1[2][d]; a3 += acc1[3][d];
        int base = (g * 4) * HEADD + d;
        outT[(size_t)(base)*BATCH + b]         = a0 * inv_s[0];
        outT[(size_t)(base + 128) * BATCH + b] = a1 * inv_s[1];
        outT[(size_t)(base + 256) * BATCH + b] = a2 * inv_s[2];
        outT[(size_t)(base + 384) * BATCH + b] = a3 * inv_s[3];
    }
}

// ---------- launch ----------
extern "C" void kernel_launch(void* const* d_in, const int* in_sizes, int n_in,
                              void* d_out, int out_size)
{
    const float* x     = (const float*)d_in[0];
    const float* fcos  = (const float*)d_in[2];
    const float* fsin  = (const float*)d_in[3];
    const float* cachek = (const float*)d_in[4];
    const float* cachev = (const float*)d_in[5];
    const float* wq = (const float*)d_in[6];
    const float* wk = (const float*)d_in[7];
    const float* wv = (const float*)d_in[8];
    const float* wo = (const float*)d_in[9];
    const float* w1 = (const float*)d_in[10];
    const float* w2 = (const float*)d_in[11];
    const float* w3 = (const float*)d_in[12];
    const float* anw = (const float*)d_in[13];
    const float* fnw = (const float*)d_in[14];
    float* out = (float*)d_out;

    float *p_hT, *p_q, *p_knew, *p_vnew, *p_attnT, *p_res2, *p_h2T, *p_gateT;
    float2 *p_P1, *p_P2;
    cudaGetSymbolAddress((void**)&p_hT, g_hT);
    cudaGetSymbolAddress((void**)&p_q, g_q);
    cudaGetSymbolAddress((void**)&p_knew, g_knew);
    cudaGetSymbolAddress((void**)&p_vnew, g_vnew);
    cudaGetSymbolAddress((void**)&p_attnT, g_attnT);
    cudaGetSymbolAddress((void**)&p_res2, g_res2);
    cudaGetSymbolAddress((void**)&p_h2T, g_h2T);
    cudaGetSymbolAddress((void**)&p_gateT, g_gateT);
    cudaGetSymbolAddress((void**)&p_P1, g_P1);
    cudaGetSymbolAddress((void**)&p_P2, g_P2);

    // 1. rmsnorm (attn)
    rmsnorm_kernel<<<32, 256>>>(x, anw, p_hT);
    // 2. fused QKV GEMV, split-K 32 (kchunk=128)
    gemv_qkv_kernel<<<dim3(12, 32), 256>>>(p_hT, wq, wk, wv, p_P1, 128);
    // 3. reduce + RoPE
    reduce_qkv_rope_kernel<<<12, 256>>>(p_P1, fcos, fsin, p_q, p_knew, p_vnew);
    // 4. attention
    attn_kernel<<<dim3(8, 32), 256>>>(cachek, cachev, p_q, p_knew, p_vnew, p_attnT);
    // 5. wo GEMV, split-K 32 (kchunk=128)
    gemv_single_kernel<<<dim3(8, 32), 256>>>(p_attnT, wo, p_P1, 4096, 4096, 128);
    // 6. reduce + residual(x)
    reduce_addres_kernel<<<16, 256>>>(p_P1, x, p_res2, 4096, 32);
    // 7. rmsnorm (ffn)
    rmsnorm_kernel<<<32, 256>>>(p_res2, fnw, p_h2T);
    // 8. gate GEMV (w1,w3), split-K 16 (kchunk=256)
    gemv_gate_kernel<<<dim3(43, 16), 256>>>(p_h2T, w1, w3, p_P1, p_P2, 256);
    // 9. reduce gate -> silu(a1)*a3, transposed
    reduce_gate_kernel<<<43, 256>>>(p_P1, p_P2, p_gateT);
    // 10. down GEMV (w2), K=11008, split-K 32 (kchunk=384, tail blocks idle)
    gemv_single_kernel<<<dim3(8, 32), 256>>>(p_gateT, w2, p_P1, 11008, 4096, 384);
    // 11. reduce + residual -> out
    reduce_addres_kernel<<<16, 256>>>(p_P1, p_res2, out, 4096, 32);
}

// round 2
// speedup vs baseline: 1.2074x; 1.2074x over previous
#include <cuda_runtime.h>
#include <math.h>

#define DIMM 4096
#define HEADD 128
#define NHQ 32
#define NHKV 8
#define HIDDEN 11008
#define BATCH 32
#define MAXSEQ 2048
#define STARTPOS 1024
#define SEQL (STARTPOS + 1)
#define EPS 1e-5f
#define KT 128

typedef unsigned long long u64;

__device__ __forceinline__ u64 fma2(u64 a, u64 b, u64 c) {
    u64 d;
    asm("fma.rn.f32x2 %0, %1, %2, %3;" : "=l"(d) : "l"(a), "l"(b), "l"(c));
    return d;
}
__device__ __forceinline__ u64 bcast2(float x) {
    u64 r;
    asm("mov.b64 %0, {%1, %1};" : "=l"(r) : "f"(x));
    return r;
}
__device__ __forceinline__ float2 unpk(u64 a) {
    float2 f;
    asm("mov.b64 {%0, %1}, %2;" : "=f"(f.x), "=f"(f.y) : "l"(a));
    return f;
}

// ---------- scratch ----------
__device__ __align__(16) float g_hT[DIMM * BATCH];
__device__ __align__(16) float g_q[BATCH * NHQ * HEADD];
__device__ __align__(16) float g_knew[BATCH * NHKV * HEADD];
__device__ __align__(16) float g_vnew[BATCH * NHKV * HEADD];
__device__ __align__(16) float g_attnT[DIMM * BATCH];
__device__ __align__(16) float g_res2[BATCH * DIMM];
__device__ __align__(16) float g_h2T[DIMM * BATCH];
__device__ __align__(16) float g_gateT[HIDDEN * BATCH];
__device__ __align__(16) float g_P1[32 * 6144 * 32];     // 25.2 MB partials
__device__ __align__(16) float g_P2[16 * 11008 * 32];    // 22.5 MB partials
__device__ __align__(16) float g_apart[NHKV * BATCH * 4 * 520]; // attn partials

// ---------- rmsnorm: x b-major -> yT[k][b] ----------
__global__ void __launch_bounds__(256) rmsnorm_kernel(
    const float* __restrict__ x, const float* __restrict__ w, float* __restrict__ yT)
{
    int b = blockIdx.x;
    const float* xr = x + (size_t)b * DIMM;
    __shared__ float red[32];
    float ss = 0.f;
    for (int i = threadIdx.x; i < DIMM; i += 256) { float v = xr[i]; ss += v * v; }
    #pragma unroll
    for (int o = 16; o; o >>= 1) ss += __shfl_xor_sync(0xffffffffu, ss, o);
    if ((threadIdx.x & 31) == 0) red[threadIdx.x >> 5] = ss;
    __syncthreads();
    if (threadIdx.x < 32) {
        float v = (threadIdx.x < 8) ? red[threadIdx.x] : 0.f;
        #pragma unroll
        for (int o = 16; o; o >>= 1) v += __shfl_xor_sync(0xffffffffu, v, o);
        if (threadIdx.x == 0) red[0] = v;
    }
    __syncthreads();
    float inv = 1.0f / (sqrtf(red[0] * (1.0f / DIMM)) + EPS);
    for (int i = threadIdx.x; i < DIMM; i += 256)
        yT[(size_t)i * BATCH + b] = w[i] * xr[i] * inv;
}

// ---------- GEMV core: thread = 4 consecutive cols x 16 batches ----------
// XT layout: [k][32 batches]. W row-major [K][ldW]. Pout points at
// P[(kz*NP + col)*32 + h*16]; col stride in P is 32 floats.
__device__ __forceinline__ void gemv4(
    const float* __restrict__ XT, const float* __restrict__ W, int ldW,
    int col, int k0, int k1, int h, float* __restrict__ Pout)
{
    __shared__ __align__(16) float sh[KT * 32];
    u64 acc[4][8];
    #pragma unroll
    for (int c = 0; c < 4; c++)
        #pragma unroll
        for (int j = 0; j < 8; j++) acc[c][j] = 0ull;

    for (int kt = k0; kt < k1; kt += KT) {
        const float4* src = (const float4*)(XT + (size_t)kt * 32);
        float4* dst = (float4*)sh;
        #pragma unroll
        for (int i = 0; i < 4; i++) dst[threadIdx.x + i * 256] = src[threadIdx.x + i * 256];
        __syncthreads();
        const float* wp = W + (size_t)kt * ldW + col;
        #pragma unroll 4
        for (int k = 0; k < KT; k++) {
            float4 w = *(const float4*)(wp + (size_t)k * ldW);
            u64 w0 = bcast2(w.x), w1 = bcast2(w.y), w2 = bcast2(w.z), w3 = bcast2(w.w);
            const u64* hb = (const u64*)(sh + k * 32 + h * 16);
            #pragma unroll
            for (int j = 0; j < 8; j++) {
                u64 hv = hb[j];
                acc[0][j] = fma2(hv, w0, acc[0][j]);
                acc[1][j] = fma2(hv, w1, acc[1][j]);
                acc[2][j] = fma2(hv, w2, acc[2][j]);
                acc[3][j] = fma2(hv, w3, acc[3][j]);
            }
        }
        __syncthreads();
    }
    #pragma unroll
    for (int c = 0; c < 4; c++) {
        #pragma unroll
        for (int j = 0; j < 4; j++) {
            float2 lo = unpk(acc[c][2 * j]), hi = unpk(acc[c][2 * j + 1]);
            *(float4*)(Pout + (size_t)c * 32 + 4 * j) = make_float4(lo.x, lo.y, hi.x, hi.y);
        }
    }
}

// fused qkv: global cols 0..4095 wq, 4096..5119 wk, 5120..6143 wv
__global__ void __launch_bounds__(256) gemv_qkv_kernel(
    const float* __restrict__ XT, const float* __restrict__ wq,
    const float* __restrict__ wk, const float* __restrict__ wv,
    float* __restrict__ P)
{
    int c = threadIdx.x & 127, h = threadIdx.x >> 7;
    int nbase = blockIdx.x * 512;
    const float* W; int ld, nloc;
    if (nbase < 4096)      { W = wq; ld = 4096; nloc = nbase; }
    else if (nbase < 5120) { W = wk; ld = 1024; nloc = nbase - 4096; }
    else                   { W = wv; ld = 1024; nloc = nbase - 5120; }
    int k0 = blockIdx.y * KT;
    gemv4(XT, W, ld, nloc + 4 * c, k0, k0 + KT, h,
          P + ((size_t)blockIdx.y * 6144 + nbase + 4 * c) * 32 + h * 16);
}

__global__ void __launch_bounds__(256) gemv_single_kernel(
    const float* __restrict__ XT, const float* __restrict__ W,
    float* __restrict__ P, int K, int N, int kchunk)
{
    int c = threadIdx.x & 127, h = threadIdx.x >> 7;
    int nbase = blockIdx.x * 512;
    int k0 = blockIdx.y * kchunk;
    int k1 = min(k0 + kchunk, K);
    gemv4(XT, W, N, nbase + 4 * c, k0, k1, h,
          P + ((size_t)blockIdx.y * N + nbase + 4 * c) * 32 + h * 16);
}

// gate: thread = 2 cols x 2 matrices x 16 batches
__global__ void __launch_bounds__(256) gemv_gate_kernel(
    const float* __restrict__ XT, const float* __restrict__ W1, const float* __restrict__ W3,
    float* __restrict__ P1, float* __restrict__ P2, int kchunk)
{
    __shared__ __align__(16) float sh[KT * 32];
    int c = threadIdx.x & 127, h = threadIdx.x >> 7;
    int n = blockIdx.x * 256 + 2 * c;
    u64 a1[2][8], a3[2][8];
    #pragma unroll
    for (int cc = 0; cc < 2; cc++)
        #pragma unroll
        for (int j = 0; j < 8; j++) { a1[cc][j] = 0ull; a3[cc][j] = 0ull; }
    int k0 = blockIdx.y * kchunk, k1 = k0 + kchunk;
    for (int kt = k0; kt < k1; kt += KT) {
        const float4* src = (const float4*)(XT + (size_t)kt * 32);
        float4* dst = (float4*)sh;
        #pragma unroll
        for (int i = 0; i < 4; i++) dst[threadIdx.x + i * 256] = src[threadIdx.x + i * 256];
        __syncthreads();
        const float* p1 = W1 + (size_t)kt * HIDDEN + n;
        const float* p3 = W3 + (size_t)kt * HIDDEN + n;
        #pragma unroll 4
        for (int k = 0; k < KT; k++) {
            float2 wa = *(const float2*)(p1 + (size_t)k * HIDDEN);
            float2 wb = *(const float2*)(p3 + (size_t)k * HIDDEN);
            u64 wa0 = bcast2(wa.x), wa1 = bcast2(wa.y);
            u64 wb0 = bcast2(wb.x), wb1 = bcast2(wb.y);
            const u64* hb = (const u64*)(sh + k * 32 + h * 16);
            #pragma unroll
            for (int j = 0; j < 8; j++) {
                u64 hv = hb[j];
                a1[0][j] = fma2(hv, wa0, a1[0][j]);
                a1[1][j] = fma2(hv, wa1, a1[1][j]);
                a3[0][j] = fma2(hv, wb0, a3[0][j]);
                a3[1][j] = fma2(hv, wb1, a3[1][j]);
            }
        }
        __syncthreads();
    }
    size_t off = ((size_t)blockIdx.y * HIDDEN + n) * 32 + h * 16;
    #pragma unroll
    for (int cc = 0; cc < 2; cc++) {
        #pragma unroll
        for (int j = 0; j < 4; j++) {
            float2 lo = unpk(a1[cc][2 * j]), hi = unpk(a1[cc][2 * j + 1]);
            *(float4*)(P1 + off + (size_t)cc * 32 + 4 * j) = make_float4(lo.x, lo.y, hi.x, hi.y);
            float2 lo3 = unpk(a3[cc][2 * j]), hi3 = unpk(a3[cc][2 * j + 1]);
            *(float4*)(P2 + off + (size_t)cc * 32 + 4 * j) = make_float4(lo3.x, lo3.y, hi3.x, hi3.y);
        }
    }
}

// ---------- reduces ----------
// qkv reduce + RoPE. Thread = 4 consecutive cols (2 rope pairs) x 16 batches.
__global__ void __launch_bounds__(256) reduce_qkv_rope_kernel(
    const float* __restrict__ P, const float* __restrict__ fcos, const float* __restrict__ fsin,
    float* __restrict__ q, float* __restrict__ knew, float* __restrict__ vnew)
{
    int c = threadIdx.x & 127, h = threadIdx.x >> 7;
    int colg = blockIdx.x * 512 + 4 * c;
    float4 a[4][4];
    #pragma unroll
    for (int cc = 0; cc < 4; cc++)
        #pragma unroll
        for (int j = 0; j < 4; j++) a[cc][j] = make_float4(0.f, 0.f, 0.f, 0.f);
    for (int kz = 0; kz < 32; kz++) {
        const float* p = P + ((size_t)kz * 6144 + colg) * 32 + h * 16;
        #pragma unroll
        for (int cc = 0; cc < 4; cc++)
            #pragma unroll
            for (int j = 0; j < 4; j++) {
                float4 u = *(const float4*)(p + (size_t)cc * 32 + 4 * j);
                a[cc][j].x += u.x; a[cc][j].y += u.y; a[cc][j].z += u.z; a[cc][j].w += u.w;
            }
    }
    int d0 = colg & 127;
    if (colg < 5120) {
        int i0 = d0 >> 1;
        float c0 = fcos[i0], s0 = fsin[i0];
        float c1 = fcos[i0 + 1], s1 = fsin[i0 + 1];
        float* dst; int head, H;
        if (colg < 4096) { head = colg >> 7; dst = q; H = NHQ; }
        else { head = (colg - 4096) >> 7; dst = knew; H = NHKV; }
        #pragma unroll
        for (int j = 0; j < 4; j++) {
            #pragma unroll
            for (int e = 0; e < 4; e++) {
                int b = h * 16 + 4 * j + e;
                float x0 = (e == 0 ? a[0][j].x : e == 1 ? a[0][j].y : e == 2 ? a[0][j].z : a[0][j].w);
                float x1 = (e == 0 ? a[1][j].x : e == 1 ? a[1][j].y : e == 2 ? a[1][j].z : a[1][j].w);
                float x2 = (e == 0 ? a[2][j].x : e == 1 ? a[2][j].y : e == 2 ? a[2][j].z : a[2][j].w);
                float x3 = (e == 0 ? a[3][j].x : e == 1 ? a[3][j].y : e == 2 ? a[3][j].z : a[3][j].w);
                float* o = dst + ((size_t)b * H + head) * HEADD + d0;
                o[0] = x0 * c0 - x1 * s0;
                o[1] = x0 * s0 + x1 * c0;
                o[2] = x2 * c1 - x3 * s1;
                o[3] = x2 * s1 + x3 * c1;
            }
        }
    } else {
        int g = (colg - 5120) >> 7;
        #pragma unroll
        for (int j = 0; j < 4; j++) {
            #pragma unroll
            for (int e = 0; e < 4; e++) {
                int b = h * 16 + 4 * j + e;
                float x0 = (e == 0 ? a[0][j].x : e == 1 ? a[0][j].y : e == 2 ? a[0][j].z : a[0][j].w);
                float x1 = (e == 0 ? a[1][j].x : e == 1 ? a[1][j].y : e == 2 ? a[1][j].z : a[1][j].w);
                float x2 = (e == 0 ? a[2][j].x : e == 1 ? a[2][j].y : e == 2 ? a[2][j].z : a[2][j].w);
                float x3 = (e == 0 ? a[3][j].x : e == 1 ? a[3][j].y : e == 2 ? a[3][j].z : a[3][j].w);
                float* o = vnew + ((size_t)b * NHKV + g) * HEADD + d0;
                o[0] = x0; o[1] = x1; o[2] = x2; o[3] = x3;
            }
        }
    }
}

// sum partials + residual (both b-major [b][N])
__global__ void __launch_bounds__(256) reduce_addres_kernel(
    const float* __restrict__ P, const float* __restrict__ res, float* __restrict__ out,
    int N, int SK)
{
    int c = threadIdx.x & 127, h = threadIdx.x >> 7;
    int n = blockIdx.x * 128 + c;
    float4 a[4];
    #pragma unroll
    for (int j = 0; j < 4; j++) a[j] = make_float4(0.f, 0.f, 0.f, 0.f);
    for (int kz = 0; kz < SK; kz++) {
        const float* p = P + ((size_t)kz * N + n) * 32 + h * 16;
        #pragma unroll
        for (int j = 0; j < 4; j++) {
            float4 u = *(const float4*)(p + 4 * j);
            a[j].x += u.x; a[j].y += u.y; a[j].z += u.z; a[j].w += u.w;
        }
    }
    #pragma unroll
    for (int j = 0; j < 4; j++) {
        int b = h * 16 + 4 * j;
        out[(size_t)(b + 0) * N + n] = a[j].x + res[(size_t)(b + 0) * N + n];
        out[(size_t)(b + 1) * N + n] = a[j].y + res[(size_t)(b + 1) * N + n];
        out[(size_t)(b + 2) * N + n] = a[j].z + res[(size_t)(b + 2) * N + n];
        out[(size_t)(b + 3) * N + n] = a[j].w + res[(size_t)(b + 3) * N + n];
    }
}

// gate reduce -> silu(a1)*a3, written transposed gT[n][b]
__global__ void __launch_bounds__(256) reduce_gate_kernel(
    const float* __restrict__ P1, const float* __restrict__ P2, float* __restrict__ gT)
{
    int c = threadIdx.x & 127, h = threadIdx.x >> 7;
    int n = blockIdx.x * 128 + c;
    float4 a[4], g3[4];
    #pragma unroll
    for (int j = 0; j < 4; j++) { a[j] = make_float4(0.f, 0.f, 0.f, 0.f); g3[j] = a[j]; }
    for (int kz = 0; kz < 16; kz++) {
        const float* p1 = P1 + ((size_t)kz * HIDDEN + n) * 32 + h * 16;
        const float* p3 = P2 + ((size_t)kz * HIDDEN + n) * 32 + h * 16;
        #pragma unroll
        for (int j = 0; j < 4; j++) {
            float4 u = *(const float4*)(p1 + 4 * j);
            a[j].x += u.x; a[j].y += u.y; a[j].z += u.z; a[j].w += u.w;
            float4 w = *(const float4*)(p3 + 4 * j);
            g3[j].x += w.x; g3[j].y += w.y; g3[j].z += w.z; g3[j].w += w.w;
        }
    }
    float* dst = gT + (size_t)n * 32 + h * 16;
    #pragma unroll
    for (int j = 0; j < 4; j++) {
        float4 o;
        o.x = (a[j].x / (1.f + expf(-a[j].x))) * g3[j].x;
        o.y = (a[j].y / (1.f + expf(-a[j].y))) * g3[j].y;
        o.z = (a[j].z / (1.f + expf(-a[j].z))) * g3[j].z;
        o.w = (a[j].w / (1.f + expf(-a[j].w))) * g3[j].w;
        *(float4*)(dst + 4 * j) = o;
    }
}

// ---------- attention, split-L into 4 chunks ----------
// apart layout per (g,b,ch): [m0..m3][s0..s3][pv[4][128]] = 520 floats
__global__ void __launch_bounds__(256) attn_part_kernel(
    const float* __restrict__ cache_k, const float* __restrict__ cache_v,
    const float* __restrict__ q, const float* __restrict__ knew, const float* __restrict__ vnew,
    float* __restrict__ apart)
{
    int g = blockIdx.x, b = blockIdx.y, ch = blockIdx.z;
    int lbase = ch * 256;
    int cs = (ch == 3) ? 257 : 256;
    __shared__ __align__(16) float sc[4][272];
    __shared__ __align__(16) float qs[4][HEADD];
    __shared__ float red[8];
    __shared__ float accb[4][HEADD];
    int tid = threadIdx.x, warp = tid >> 5, lane = tid & 31;
    float* ap = apart + (size_t)((g * 32 + b) * 4 + ch) * 520;

    for (int i = tid; i < 4 * HEADD; i += 256) {
        int r = i >> 7, d = i & 127;
        qs[r][d] = q[((size_t)b * NHQ + (g * 4 + r)) * HEADD + d];
    }
    __syncthreads();
    float ql[4][4];
    #pragma unroll
    for (int r = 0; r < 4; r++) {
        float4 t = *(const float4*)&qs[r][lane * 4];
        ql[r][0] = t.x; ql[r][1] = t.y; ql[r][2] = t.z; ql[r][3] = t.w;
    }
    const float scale = 0.08838834764831845f;

    #pragma unroll 4
    for (int i = 0; i < 32; i++) {
        int l = lbase + warp + i * 8;
        const float* kp = cache_k + (((size_t)b * MAXSEQ + l) * NHKV + g) * HEADD;
        float4 kv = *(const float4*)(kp + lane * 4);
        float p0 = kv.x * ql[0][0] + kv.y * ql[0][1] + kv.z * ql[0][2] + kv.w * ql[0][3];
        float p1 = kv.x * ql[1][0] + kv.y * ql[1][1] + kv.z * ql[1][2] + kv.w * ql[1][3];
        float p2 = kv.x * ql[2][0] + kv.y * ql[2][1] + kv.z * ql[2][2] + kv.w * ql[2][3];
        float p3 = kv.x * ql[3][0] + kv.y * ql[3][1] + kv.z * ql[3][2] + kv.w * ql[3][3];
        #pragma unroll
        for (int o = 16; o; o >>= 1) {
            p0 += __shfl_xor_sync(0xffffffffu, p0, o);
            p1 += __shfl_xor_sync(0xffffffffu, p1, o);
            p2 += __shfl_xor_sync(0xffffffffu, p2, o);
            p3 += __shfl_xor_sync(0xffffffffu, p3, o);
        }
        if (lane == 0) {
            int li = warp + i * 8;
            sc[0][li] = p0 * scale; sc[1][li] = p1 * scale;
            sc[2][li] = p2 * scale; sc[3][li] = p3 * scale;
        }
    }
    if (ch == 3 && warp == 0) {
        const float* kp = knew + ((size_t)b * NHKV + g) * HEADD;
        float4 kv = *(const float4*)(kp + lane * 4);
        float p0 = kv.x * ql[0][0] + kv.y * ql[0][1] + kv.z * ql[0][2] + kv.w * ql[0][3];
        float p1 = kv.x * ql[1][0] + kv.y * ql[1][1] + kv.z * ql[1][2] + kv.w * ql[1][3];
        float p2 = kv.x * ql[2][0] + kv.y * ql[2][1] + kv.z * ql[2][2] + kv.w * ql[2][3];
        float p3 = kv.x * ql[3][0] + kv.y * ql[3][1] + kv.z * ql[3][2] + kv.w * ql[3][3];
        #pragma unroll
        for (int o = 16; o; o >>= 1) {
            p0 += __shfl_xor_sync(0xffffffffu, p0, o);
            p1 += __shfl_xor_sync(0xffffffffu, p1, o);
            p2 += __shfl_xor_sync(0xffffffffu, p2, o);
            p3 += __shfl_xor_sync(0xffffffffu, p3, o);
        }
        if (lane == 0) {
            sc[0][256] = p0 * scale; sc[1][256] = p1 * scale;
            sc[2][256] = p2 * scale; sc[3][256] = p3 * scale;
        }
    }
    __syncthreads();

    // partial softmax per head (64 threads each)
    {
        int r = tid >> 6, t = tid & 63;
        float m = -1e30f;
        for (int li = t; li < cs; li += 64) m = fmaxf(m, sc[r][li]);
        #pragma unroll
        for (int o = 16; o; o >>= 1) m = fmaxf(m, __shfl_xor_sync(0xffffffffu, m, o));
        if (lane == 0) red[warp] = m;
        __syncthreads();
        m = fmaxf(red[2 * r], red[2 * r + 1]);
        float s = 0.f;
        for (int li = t; li < cs; li += 64) {
            float e = expf(sc[r][li] - m);
            sc[r][li] = e; s += e;
        }
        #pragma unroll
        for (int o = 16; o; o >>= 1) s += __shfl_xor_sync(0xffffffffu, s, o);
        __syncthreads();
        if (lane == 0) red[warp] = s;
        __syncthreads();
        s = red[2 * r] + red[2 * r + 1];
        if (t == 0) { ap[r] = m; ap[4 + r] = s; }
    }
    __syncthreads();

    // partial weighted V
    int d = tid & 127, half = tid >> 7;
    float a0 = 0, a1 = 0, a2 = 0, a3 = 0;
    #pragma unroll 4
    for (int li = half; li < cs; li += 2) {
        int l = lbase + li;
        const float* vp = (l < STARTPOS)
            ? cache_v + (((size_t)b * MAXSEQ + l) * NHKV + g) * HEADD
            : vnew + ((size_t)b * NHKV + g) * HEADD;
        float v = vp[d];
        a0 += sc[0][li] * v; a1 += sc[1][li] * v; a2 += sc[2][li] * v; a3 += sc[3][li] * v;
    }
    if (half == 1) { accb[0][d] = a0; accb[1][d] = a1; accb[2][d] = a2; accb[3][d] = a3; }
    __syncthreads();
    if (half == 0) {
        a0 += accb[0][d]; a1 += accb[1][d]; a2 += accb[2][d]; a3 += accb[3][d];
        ap[8 + 0 * 128 + d] = a0;
        ap[8 + 1 * 128 + d] = a1;
        ap[8 + 2 * 128 + d] = a2;
        ap[8 + 3 * 128 + d] = a3;
    }
}

__global__ void __launch_bounds__(128) attn_combine_kernel(
    const float* __restrict__ apart, float* __restrict__ attnT)
{
    int g = blockIdx.x, b = blockIdx.y, d = threadIdx.x;
    const float* base = apart + (size_t)((g * 32 + b) * 4) * 520;
    #pragma unroll
    for (int r = 0; r < 4; r++) {
        float m0 = base[0 * 520 + r], m1 = base[1 * 520 + r];
        float m2 = base[2 * 520 + r], m3 = base[3 * 520 + r];
        float M = fmaxf(fmaxf(m0, m1), fmaxf(m2, m3));
        float w0 = expf(m0 - M), w1 = expf(m1 - M), w2 = expf(m2 - M), w3 = expf(m3 - M);
        float denom = base[0 * 520 + 4 + r] * w0 + base[1 * 520 + 4 + r] * w1
                    + base[2 * 520 + 4 + r] * w2 + base[3 * 520 + 4 + r] * w3;
        float o = base[0 * 520 + 8 + r * 128 + d] * w0 + base[1 * 520 + 8 + r * 128 + d] * w1
                + base[2 * 520 + 8 + r * 128 + d] * w2 + base[3 * 520 + 8 + r * 128 + d] * w3;
        attnT[(size_t)((g * 4 + r) * 128 + d) * 32 + b] = o / denom;
    }
}

// ---------- launch ----------
extern "C" void kernel_launch(void* const* d_in, const int* in_sizes, int n_in,
                              void* d_out, int out_size)
{
    const float* x     = (const float*)d_in[0];
    const float* fcos  = (const float*)d_in[2];
    const float* fsin  = (const float*)d_in[3];
    const float* cachek = (const float*)d_in[4];
    const float* cachev = (const float*)d_in[5];
    const float* wq = (const float*)d_in[6];
    const float* wk = (const float*)d_in[7];
    const float* wv = (const float*)d_in[8];
    const float* wo = (const float*)d_in[9];
    const float* w1 = (const float*)d_in[10];
    const float* w2 = (const float*)d_in[11];
    const float* w3 = (const float*)d_in[12];
    const float* anw = (const float*)d_in[13];
    const float* fnw = (const float*)d_in[14];
    float* out = (float*)d_out;

    float *p_hT, *p_q, *p_knew, *p_vnew, *p_attnT, *p_res2, *p_h2T, *p_gateT, *p_P1, *p_P2, *p_apart;
    cudaGetSymbolAddress((void**)&p_hT, g_hT);
    cudaGetSymbolAddress((void**)&p_q, g_q);
    cudaGetSymbolAddress((void**)&p_knew, g_knew);
    cudaGetSymbolAddress((void**)&p_vnew, g_vnew);
    cudaGetSymbolAddress((void**)&p_attnT, g_attnT);
    cudaGetSymbolAddress((void**)&p_res2, g_res2);
    cudaGetSymbolAddress((void**)&p_h2T, g_h2T);
    cudaGetSymbolAddress((void**)&p_gateT, g_gateT);
    cudaGetSymbolAddress((void**)&p_P1, g_P1);
    cudaGetSymbolAddress((void**)&p_P2, g_P2);
    cudaGetSymbolAddress((void**)&p_apart, g_apart);

    rmsnorm_kernel<<<32, 256>>>(x, anw, p_hT);
    gemv_qkv_kernel<<<dim3(12, 32), 256>>>(p_hT, wq, wk, wv, p_P1);
    reduce_qkv_rope_kernel<<<12, 256>>>(p_P1, fcos, fsin, p_q, p_knew, p_vnew);
    attn_part_kernel<<<dim3(8, 32, 4), 256>>>(cachek, cachev, p_q, p_knew, p_vnew, p_apart);
    attn_combine_kernel<<<dim3(8, 32), 128>>>(p_apart, p_attnT);
    gemv_single_kernel<<<dim3(8, 32), 256>>>(p_attnT, wo, p_P1, 4096, 4096, 128);
    reduce_addres_kernel<<<32, 256>>>(p_P1, x, p_res2, 4096, 32);
    rmsnorm_kernel<<<32, 256>>>(p_res2, fnw, p_h2T);
    gemv_gate_kernel<<<dim3(43, 16), 256>>>(p_h2T, w1, w3, p_P1, p_P2, 256);
    reduce_gate_kernel<<<86, 256>>>(p_P1, p_P2, p_gateT);
    gemv_single_kernel<<<dim3(8, 43), 256>>>(p_gateT, w2, p_P1, 11008, 4096, 256);
    reduce_addres_kernel<<<32, 256>>>(p_P1, p_res2, out, 4096, 43);
}